// round 7
// baseline (speedup 1.0000x reference)
#include <cuda_runtime.h>
#include <cuda_bf16.h>

// SimpleLSS: softmax over depth sums to 1 -> weighted == img_feat.
// Whole op == bilinear upsample (24,256,16,44) -> (24,256,128,128),
// half-pixel centers, clamped edges. depth_logits never read.
//
// R7: R3 (best, 59.9us) with default-policy stores instead of .cs.
// Isolates whether evict-first streaming policy fragments the L2->DRAM
// write drain. Everything else identical to R3.

#define IN_H 16
#define IN_W 44
#define OUT_HW 128
#define PLANE_IN (IN_H * IN_W)      // 704
#define PLANE_OUT (OUT_HW * OUT_HW) // 16384

__global__ __launch_bounds__(256) void lss_resize_kernel(
    const float* __restrict__ img, float* __restrict__ out)
{
    const int plane = blockIdx.x;                 // n*256 + c
    const float* __restrict__ src = img + (long long)plane * PLANE_IN;
    float* __restrict__ dst = out + (long long)plane * PLANE_OUT;

    __shared__ float tile[PLANE_IN];          // raw 16x44 input
    __shared__ float4 hrow[IN_H * 32];        // 16 rows x 128 floats (as float4)

    // ---- load input plane (704 floats) ----
    for (int i = threadIdx.x; i < PLANE_IN; i += 256)
        tile[i] = src[i];
    __syncthreads();

    // ---- stage 1: horizontal interp, 16*128 = 2048 values, 8/thread ----
    float* hrow_s = reinterpret_cast<float*>(hrow);
    #pragma unroll
    for (int k = 0; k < 8; ++k) {
        const int i = k * 256 + threadIdx.x;
        const int r = i >> 7;            // input row 0..15
        const int x = i & 127;           // output col 0..127
        // horizontal scale 44/128 = 0.34375 (exact fp32)
        float sx = fmaxf(((float)x + 0.5f) * 0.34375f - 0.5f, 0.0f);
        int   x0 = (int)sx;
        float fx = sx - (float)x0;
        int   x1 = min(x0 + 1, IN_W - 1);
        const float* rp = tile + r * IN_W;
        float v0 = rp[x0];
        hrow_s[i] = v0 + fx * (rp[x1] - v0);
    }
    __syncthreads();

    // ---- stage 2: vertical blend from registers ----
    // Warp layout: lane c owns x-chunk [4c, 4c+3]; warp w handles row
    // groups g = w and g = w+8. Group g covers output rows 8g+4..8g+11
    // (fy = 0.0625 + 0.125*r); group 0 also emits rows 0-3 (fy=0);
    // group 15's b clamps to hrow[15]; rows >= 128 skipped.
    const int c = threadIdx.x & 31;      // x-chunk index
    const int w = threadIdx.x >> 5;      // warp id 0..7
    const int x = c * 4;

    #pragma unroll
    for (int s = 0; s < 2; ++s) {
        const int g = w + 8 * s;                         // 0..15
        float4 a = hrow[g * 32 + c];
        float4 b = hrow[min(g + 1, IN_H - 1) * 32 + c];
        float4 d;
        d.x = b.x - a.x; d.y = b.y - a.y;
        d.z = b.z - a.z; d.w = b.w - a.w;

        if (g == 0) {
            #pragma unroll
            for (int r = 0; r < 4; ++r)
                *reinterpret_cast<float4*>(dst + r * OUT_HW + x) = a;
        }

        #pragma unroll
        for (int r = 0; r < 8; ++r) {
            const int y = 8 * g + 4 + r;
            if (y < OUT_HW) {
                const float fy = 0.0625f + 0.125f * (float)r;
                float4 v;
                v.x = a.x + fy * d.x;
                v.y = a.y + fy * d.y;
                v.z = a.z + fy * d.z;
                v.w = a.w + fy * d.w;
                *reinterpret_cast<float4*>(dst + y * OUT_HW + x) = v;
            }
        }
    }
}

extern "C" void kernel_launch(void* const* d_in, const int* in_sizes, int n_in,
                              void* d_out, int out_size)
{
    const float* img = (const float*)d_in[0];   // (24,256,16,44)
    float* out = (float*)d_out;                 // (24,256,128,128)
    const int planes = in_sizes[0] / PLANE_IN;  // 6144
    lss_resize_kernel<<<planes, 256>>>(img, out);
}

// round 8
// speedup vs baseline: 1.1362x; 1.1362x over previous
#include <cuda_runtime.h>
#include <cuda_bf16.h>

// SimpleLSS: softmax over depth sums to 1 -> weighted == img_feat.
// Whole op == bilinear upsample (24,256,16,44) -> (24,256,128,128),
// half-pixel centers, clamped edges. depth_logits never read.
//
// FINAL (== R3, 59.9us): separable interp, register-blocked vertical pass,
// .cs streaming stores. 403MB output / 59.9us = 6.7 TB/s — measured HBM
// write floor on this part. R4 (TMA staging), R6 (v8 stores), R7 (default
// store policy) all regressed; .cs is load-bearing for back-to-back graph
// replays (keeps L2 clean of dirty output lines between iterations).

#define IN_H 16
#define IN_W 44
#define OUT_HW 128
#define PLANE_IN (IN_H * IN_W)      // 704
#define PLANE_OUT (OUT_HW * OUT_HW) // 16384

__global__ __launch_bounds__(256) void lss_resize_kernel(
    const float* __restrict__ img, float* __restrict__ out)
{
    const int plane = blockIdx.x;                 // n*256 + c
    const float* __restrict__ src = img + (long long)plane * PLANE_IN;
    float* __restrict__ dst = out + (long long)plane * PLANE_OUT;

    __shared__ float tile[PLANE_IN];          // raw 16x44 input
    __shared__ float4 hrow[IN_H * 32];        // 16 rows x 128 floats (as float4)

    // ---- load input plane (704 floats) ----
    for (int i = threadIdx.x; i < PLANE_IN; i += 256)
        tile[i] = src[i];
    __syncthreads();

    // ---- stage 1: horizontal interp, 16*128 = 2048 values, 8/thread ----
    float* hrow_s = reinterpret_cast<float*>(hrow);
    #pragma unroll
    for (int k = 0; k < 8; ++k) {
        const int i = k * 256 + threadIdx.x;
        const int r = i >> 7;            // input row 0..15
        const int x = i & 127;           // output col 0..127
        // horizontal scale 44/128 = 0.34375 (exact fp32)
        float sx = fmaxf(((float)x + 0.5f) * 0.34375f - 0.5f, 0.0f);
        int   x0 = (int)sx;
        float fx = sx - (float)x0;
        int   x1 = min(x0 + 1, IN_W - 1);
        const float* rp = tile + r * IN_W;
        float v0 = rp[x0];
        hrow_s[i] = v0 + fx * (rp[x1] - v0);
    }
    __syncthreads();

    // ---- stage 2: vertical blend from registers ----
    // Warp layout: lane c owns x-chunk [4c, 4c+3]; warp w handles row
    // groups g = w and g = w+8. Group g covers output rows 8g+4..8g+11
    // (fy = 0.0625 + 0.125*r); group 0 also emits rows 0-3 (fy = 0);
    // group 15's b clamps to hrow[15] (delta = 0); rows >= 128 skipped.
    const int c = threadIdx.x & 31;      // x-chunk index
    const int w = threadIdx.x >> 5;      // warp id 0..7
    const int x = c * 4;

    #pragma unroll
    for (int s = 0; s < 2; ++s) {
        const int g = w + 8 * s;                         // 0..15
        float4 a = hrow[g * 32 + c];
        float4 b = hrow[min(g + 1, IN_H - 1) * 32 + c];
        float4 d;
        d.x = b.x - a.x; d.y = b.y - a.y;
        d.z = b.z - a.z; d.w = b.w - a.w;

        if (g == 0) {
            #pragma unroll
            for (int r = 0; r < 4; ++r)
                __stcs(reinterpret_cast<float4*>(dst + r * OUT_HW + x), a);
        }

        #pragma unroll
        for (int r = 0; r < 8; ++r) {
            const int y = 8 * g + 4 + r;
            if (y < OUT_HW) {
                const float fy = 0.0625f + 0.125f * (float)r;
                float4 v;
                v.x = a.x + fy * d.x;
                v.y = a.y + fy * d.y;
                v.z = a.z + fy * d.z;
                v.w = a.w + fy * d.w;
                __stcs(reinterpret_cast<float4*>(dst + y * OUT_HW + x), v);
            }
        }
    }
}

extern "C" void kernel_launch(void* const* d_in, const int* in_sizes, int n_in,
                              void* d_out, int out_size)
{
    const float* img = (const float*)d_in[0];   // (24,256,16,44)
    float* out = (float*)d_out;                 // (24,256,128,128)
    const int planes = in_sizes[0] / PLANE_IN;  // 6144
    lss_resize_kernel<<<planes, 256>>>(img, out);
}

// round 9
// speedup vs baseline: 1.1410x; 1.0043x over previous
#include <cuda_runtime.h>
#include <cuda_bf16.h>

// SimpleLSS: softmax over depth sums to 1 -> weighted == img_feat.
// Whole op == bilinear upsample (24,256,16,44) -> (24,256,128,128),
// half-pixel centers, clamped edges. depth_logits never read.
//
// FINAL (== R3, 59.9us): separable interp, register-blocked vertical pass,
// .cs streaming stores. 403MB output / 59.9us = 6.7 TB/s — measured HBM
// write floor on this part. R4 (TMA staging), R6 (v8 stores), R7 (default
// store policy) all regressed; .cs is load-bearing for back-to-back graph
// replays (keeps L2 clean of dirty output lines between iterations).

#define IN_H 16
#define IN_W 44
#define OUT_HW 128
#define PLANE_IN (IN_H * IN_W)      // 704
#define PLANE_OUT (OUT_HW * OUT_HW) // 16384

__global__ __launch_bounds__(256) void lss_resize_kernel(
    const float* __restrict__ img, float* __restrict__ out)
{
    const int plane = blockIdx.x;                 // n*256 + c
    const float* __restrict__ src = img + (long long)plane * PLANE_IN;
    float* __restrict__ dst = out + (long long)plane * PLANE_OUT;

    __shared__ float tile[PLANE_IN];          // raw 16x44 input
    __shared__ float4 hrow[IN_H * 32];        // 16 rows x 128 floats (as float4)

    // ---- load input plane (704 floats) ----
    for (int i = threadIdx.x; i < PLANE_IN; i += 256)
        tile[i] = src[i];
    __syncthreads();

    // ---- stage 1: horizontal interp, 16*128 = 2048 values, 8/thread ----
    float* hrow_s = reinterpret_cast<float*>(hrow);
    #pragma unroll
    for (int k = 0; k < 8; ++k) {
        const int i = k * 256 + threadIdx.x;
        const int r = i >> 7;            // input row 0..15
        const int x = i & 127;           // output col 0..127
        // horizontal scale 44/128 = 0.34375 (exact fp32)
        float sx = fmaxf(((float)x + 0.5f) * 0.34375f - 0.5f, 0.0f);
        int   x0 = (int)sx;
        float fx = sx - (float)x0;
        int   x1 = min(x0 + 1, IN_W - 1);
        const float* rp = tile + r * IN_W;
        float v0 = rp[x0];
        hrow_s[i] = v0 + fx * (rp[x1] - v0);
    }
    __syncthreads();

    // ---- stage 2: vertical blend from registers ----
    // Warp layout: lane c owns x-chunk [4c, 4c+3]; warp w handles row
    // groups g = w and g = w+8. Group g covers output rows 8g+4..8g+11
    // (fy = 0.0625 + 0.125*r); group 0 also emits rows 0-3 (fy = 0);
    // group 15's b clamps to hrow[15] (delta = 0); rows >= 128 skipped.
    const int c = threadIdx.x & 31;      // x-chunk index
    const int w = threadIdx.x >> 5;      // warp id 0..7
    const int x = c * 4;

    #pragma unroll
    for (int s = 0; s < 2; ++s) {
        const int g = w + 8 * s;                         // 0..15
        float4 a = hrow[g * 32 + c];
        float4 b = hrow[min(g + 1, IN_H - 1) * 32 + c];
        float4 d;
        d.x = b.x - a.x; d.y = b.y - a.y;
        d.z = b.z - a.z; d.w = b.w - a.w;

        if (g == 0) {
            #pragma unroll
            for (int r = 0; r < 4; ++r)
                __stcs(reinterpret_cast<float4*>(dst + r * OUT_HW + x), a);
        }

        #pragma unroll
        for (int r = 0; r < 8; ++r) {
            const int y = 8 * g + 4 + r;
            if (y < OUT_HW) {
                const float fy = 0.0625f + 0.125f * (float)r;
                float4 v;
                v.x = a.x + fy * d.x;
                v.y = a.y + fy * d.y;
                v.z = a.z + fy * d.z;
                v.w = a.w + fy * d.w;
                __stcs(reinterpret_cast<float4*>(dst + y * OUT_HW + x), v);
            }
        }
    }
}

extern "C" void kernel_launch(void* const* d_in, const int* in_sizes, int n_in,
                              void* d_out, int out_size)
{
    const float* img = (const float*)d_in[0];   // (24,256,16,44)
    float* out = (float*)d_out;                 // (24,256,128,128)
    const int planes = in_sizes[0] / PLANE_IN;  // 6144
    lss_resize_kernel<<<planes, 256>>>(img, out);
}